// round 11
// baseline (speedup 1.0000x reference)
#include <cuda_runtime.h>
#include <cstdint>

#define NMAX 50000
#define EMAX 800000
#define DD 64
#define CSR_G 148          // one block per SM: full residency guaranteed
#define CSR_T 1024

// ------------------------- scratch (__device__ globals; no allocs) ----------
__device__ int   g_cnt[NMAX];              // in-degree (without self-loop)
__device__ int   g_rs[NMAX];               // CSR row start (exclusive scan of cnt)
__device__ int   g_cur[NMAX];              // placement cursor
__device__ int   g_bsum[CSR_G];            // per-block scan totals
__device__ unsigned g_barcnt;              // grid-barrier arrival counter (monotonic)
__device__ __align__(16) float g_dinv[NMAX];
__device__ __align__(16) int2  g_edge[EMAX];   // CSR slot: {src, norm bits}
__device__ __align__(16) float g_h[NMAX * DD];
__device__ __align__(16) float g_out1[NMAX * DD];
__device__ __align__(16) float g_out2[NMAX * DD];
__device__ __align__(16) float g_out3[NMAX * DD];
__device__ float g_conc[NMAX];
__device__ float g_sum[1];

__device__ __forceinline__ int clampi(int v, int lo, int hi) {
    return v < lo ? lo : (v > hi ? hi : v);
}

// Software grid barrier. Valid because the grid (148 blocks) is fully resident.
// Counter is monotonic across launches/replays; targets are computed relatively,
// so no reset is needed and the kernel stays deterministic.
__device__ __forceinline__ void grid_barrier() {
    __syncthreads();
    if (threadIdx.x == 0) {
        __threadfence();
        unsigned v = atomicAdd(&g_barcnt, 1u) + 1u;
        unsigned G = gridDim.x;
        unsigned target = ((v + G - 1u) / G) * G;   // end of this barrier epoch
        while (*((volatile unsigned*)&g_barcnt) < target) { }
        __threadfence();
    }
    __syncthreads();
}

// ------------------- fused CSR build: one kernel, 5 phases -------------------
__global__ void __launch_bounds__(CSR_T)
k_csr(const int* __restrict__ ei, int E, int n) {
    __shared__ int sh[CSR_T];
    int t   = threadIdx.x;
    int bid = blockIdx.x;
    int gtid = bid * CSR_T + t;
    int gstride = gridDim.x * CSR_T;

    // node chunk owned by this block for the scan phases
    int nch  = (n + CSR_G - 1) / CSR_G;       // 338
    int nbeg = bid * nch;
    int nend = min(n, nbeg + nch);

    // ---- phase 0: zero counters ----
    for (int i = gtid; i < n; i += gstride) g_cnt[i] = 0;
    if (gtid == 0) g_sum[0] = 0.0f;
    grid_barrier();

    // ---- phase 1: count in-degrees ----
    for (int e = gtid; e < E; e += gstride) {
        int d = clampi(ei[E + e], 0, n - 1);
        atomicAdd(&g_cnt[d], 1);
    }
    grid_barrier();

    // ---- phase 2: dinv + per-block exclusive scan of chunk ----
    {
        int i = nbeg + t;
        int v = (t < nch && i < nend) ? g_cnt[i] : 0;
        if (t < nch && i < nend) g_dinv[i] = rsqrtf((float)v + 1.0f);
        sh[t] = v;
        __syncthreads();
        for (int off = 1; off < CSR_T; off <<= 1) {
            int a = (t >= off) ? sh[t - off] : 0;
            __syncthreads();
            sh[t] += a;
            __syncthreads();
        }
        if (t < nch && i < nend) g_rs[i] = sh[t] - v;   // exclusive within chunk
        if (t == CSR_T - 1) g_bsum[bid] = sh[t];        // chunk total
    }
    grid_barrier();

    // ---- phase 3: add prefix of chunk totals; init cursors ----
    {
        // reduce bsum[0..bid) with the whole block
        int v = (t < bid) ? g_bsum[t] : 0;              // bid < 148 < 1024
        sh[t] = v;
        __syncthreads();
        for (int off = CSR_T / 2; off > 0; off >>= 1) {
            if (t < off) sh[t] += sh[t + off];
            __syncthreads();
        }
        int offset = sh[0];
        int i = nbeg + t;
        if (t < nch && i < nend) {
            int r = g_rs[i] + offset;
            g_rs[i]  = r;
            g_cur[i] = r;
        }
    }
    grid_barrier();

    // ---- phase 4: place edges (packed {src, norm}) ----
    for (int e = gtid; e < E; e += gstride) {
        int s = clampi(ei[e], 0, n - 1);
        int d = clampi(ei[E + e], 0, n - 1);
        int pos = atomicAdd(&g_cur[d], 1);
        float nrm = g_dinv[s] * g_dinv[d];
        g_edge[pos] = make_int2(s, __float_as_int(nrm));
    }
}

// ------------------------- GEMM: g_h = x @ W ---------------------------------
// 256 threads, 32 rows/block. float4-vectorized smem traffic.
__global__ void k_gemm(const float* __restrict__ xext, int sel,
                       const float* __restrict__ W, int n) {
    __shared__ float Ws[DD * DD];
    __shared__ float xs[32 * DD];
    const float* x = (sel == 0) ? xext : (sel == 1 ? g_out1 : g_out2);

    int tid = threadIdx.x;
    {
        const float4* W4 = (const float4*)W;
        float4* Ws4 = (float4*)Ws;
#pragma unroll
        for (int i = 0; i < 4; i++) Ws4[tid + i * 256] = W4[tid + i * 256];
    }
    int row0 = blockIdx.x * 32;
    {
        if (row0 + 32 <= n) {
            const float4* x4 = (const float4*)(x + row0 * DD);
            float4* xs4 = (float4*)xs;
            xs4[tid] = x4[tid];
            xs4[tid + 256] = x4[tid + 256];
        } else {
            int nrows = n - row0;
            for (int i = tid; i < nrows * DD; i += 256) xs[i] = x[row0 * DD + i];
        }
    }
    __syncthreads();

    int c  = tid & 63;
    int r0 = (tid >> 6) * 8;
    float acc[8];
#pragma unroll
    for (int rr = 0; rr < 8; rr++) acc[rr] = 0.0f;

#pragma unroll
    for (int kc = 0; kc < DD; kc += 4) {
        float w0 = Ws[(kc + 0) * DD + c];
        float w1 = Ws[(kc + 1) * DD + c];
        float w2 = Ws[(kc + 2) * DD + c];
        float w3 = Ws[(kc + 3) * DD + c];
#pragma unroll
        for (int rr = 0; rr < 8; rr++) {
            float4 xv = *(const float4*)&xs[(r0 + rr) * DD + kc];
            acc[rr] += xv.x * w0 + xv.y * w1 + xv.z * w2 + xv.w * w3;
        }
    }

#pragma unroll
    for (int rr = 0; rr < 8; rr++) {
        int r = row0 + r0 + rr;
        if (r < n) g_h[r * DD + c] = acc[rr];
    }
}

// ---- aggregate: out = relu( sum_in norm*h[src] + h[node]*dinv^2 + b ) -------
// warp per node; lane covers channels 2*lane, 2*lane+1 (float2);
// 4-edge pipelined loop, two accumulator pairs.
__global__ void k_agg(const float* __restrict__ b, int sel, int n) {
    int node = (int)((blockIdx.x * (unsigned)blockDim.x + threadIdx.x) >> 5);
    int lane = threadIdx.x & 31;
    if (node >= n) return;

    int ch = lane * 2;
    float di = g_dinv[node];
    float sl = di * di;
    float2 hv = *(const float2*)&g_h[node * DD + ch];
    float2 bb = *(const float2*)&b[ch];
    float a0 = hv.x * sl + bb.x;
    float a1 = hv.y * sl + bb.y;
    float c0 = 0.0f, c1 = 0.0f;

    int j   = g_rs[node];
    int end = j + g_cnt[node];

    if ((j & 1) && j < end) {
        int2 e0 = g_edge[j++];
        float n0 = __int_as_float(e0.y);
        float2 v0 = *(const float2*)&g_h[e0.x * DD + ch];
        a0 += n0 * v0.x;
        a1 += n0 * v0.y;
    }
    for (; j + 3 < end; j += 4) {
        int4 ea = *(const int4*)&g_edge[j];
        int4 eb = *(const int4*)&g_edge[j + 2];
        float n0 = __int_as_float(ea.y);
        float n1 = __int_as_float(ea.w);
        float n2 = __int_as_float(eb.y);
        float n3 = __int_as_float(eb.w);
        float2 v0 = *(const float2*)&g_h[ea.x * DD + ch];
        float2 v1 = *(const float2*)&g_h[ea.z * DD + ch];
        float2 v2 = *(const float2*)&g_h[eb.x * DD + ch];
        float2 v3 = *(const float2*)&g_h[eb.z * DD + ch];
        a0 += n0 * v0.x + n1 * v1.x;
        a1 += n0 * v0.y + n1 * v1.y;
        c0 += n2 * v2.x + n3 * v3.x;
        c1 += n2 * v2.y + n3 * v3.y;
    }
    if (j + 1 < end) {
        int4 ee = *(const int4*)&g_edge[j];
        float n0 = __int_as_float(ee.y);
        float n1 = __int_as_float(ee.w);
        float2 v0 = *(const float2*)&g_h[ee.x * DD + ch];
        float2 v1 = *(const float2*)&g_h[ee.z * DD + ch];
        a0 += n0 * v0.x + n1 * v1.x;
        a1 += n0 * v0.y + n1 * v1.y;
        j += 2;
    }
    if (j < end) {
        int2 e0 = g_edge[j];
        float n0 = __int_as_float(e0.y);
        float2 v0 = *(const float2*)&g_h[e0.x * DD + ch];
        a0 += n0 * v0.x;
        a1 += n0 * v0.y;
    }
    a0 += c0;
    a1 += c1;

    float* out = (sel == 1) ? g_out1 : (sel == 2 ? g_out2 : g_out3);
    *(float2*)&out[node * DD + ch] = make_float2(fmaxf(a0, 0.0f), fmaxf(a1, 0.0f));
}

// ------------------------- MLP head: GEMM-style layer1 -----------------------
// 256 threads = 8 warps; warp handles 8 nodes; lane = output column (32 outs).
__global__ void k_mlp(const float* __restrict__ state,
                      const float* __restrict__ lw1, const float* __restrict__ lb1,
                      const float* __restrict__ lw2, const float* __restrict__ lb2,
                      const float* __restrict__ lw3, const float* __restrict__ lb3,
                      int n) {
    __shared__ float s_w1[256 * 32];   // 32 KB  [k][o]
    __shared__ float s_w2[32 * 32];    // [i][o]
    __shared__ float s_w3[32];
    __shared__ float s_b1[32];
    __shared__ float s_b2[32];
    __shared__ float s_h1[64 * 32];    // 8 KB
    __shared__ float s_blk[8];

    int tid = threadIdx.x;
    {
        const float4* a = (const float4*)lw1;
        float4* d = (float4*)s_w1;
#pragma unroll
        for (int i = 0; i < 8; i++) d[tid + i * 256] = a[tid + i * 256];
    }
    for (int i = tid; i < 32 * 32; i += 256) s_w2[i] = lw2[i];
    if (tid < 32) { s_w3[tid] = lw3[tid]; s_b1[tid] = lb1[tid]; s_b2[tid] = lb2[tid]; }
    __syncthreads();

    int warp = tid >> 5, lane = tid & 31;
    int node0 = blockIdx.x * 64 + warp * 8;

    float acc[8];
#pragma unroll
    for (int rr = 0; rr < 8; rr++) acc[rr] = s_b1[lane];

    const float* segs[4] = {g_out1, g_out2, g_out3, state};
    bool full8 = (node0 + 8 <= n);

#pragma unroll
    for (int sg = 0; sg < 4; sg++) {
        const float* xp = segs[sg] + (size_t)node0 * DD;
#pragma unroll
        for (int kc = 0; kc < DD; kc += 4) {
            int k = sg * DD + kc;
            float w0 = s_w1[(k + 0) * 32 + lane];
            float w1 = s_w1[(k + 1) * 32 + lane];
            float w2 = s_w1[(k + 2) * 32 + lane];
            float w3 = s_w1[(k + 3) * 32 + lane];
            if (full8) {
#pragma unroll
                for (int rr = 0; rr < 8; rr++) {
                    float4 xv = *(const float4*)&xp[rr * DD + kc];  // warp-broadcast
                    acc[rr] += xv.x * w0 + xv.y * w1 + xv.z * w2 + xv.w * w3;
                }
            } else {
#pragma unroll
                for (int rr = 0; rr < 8; rr++) {
                    if (node0 + rr < n) {
                        float4 xv = *(const float4*)&xp[rr * DD + kc];
                        acc[rr] += xv.x * w0 + xv.y * w1 + xv.z * w2 + xv.w * w3;
                    }
                }
            }
        }
    }
#pragma unroll
    for (int rr = 0; rr < 8; rr++) {
        float v = acc[rr];
        s_h1[(warp * 8 + rr) * 32 + lane] = v > 0.0f ? v : 0.01f * v;
    }
    __syncwarp();

    float wsum = 0.0f;
#pragma unroll
    for (int rr = 0; rr < 8; rr++) {
        int node = node0 + rr;
        if (node >= n) break;
        const float* h1p = &s_h1[(warp * 8 + rr) * 32];
        float acc2 = s_b2[lane];
#pragma unroll
        for (int i = 0; i < 32; i++)
            acc2 += h1p[i] * s_w2[i * 32 + lane];    // h1p[i] LDS-broadcast
        float h2 = acc2 > 0.0f ? acc2 : 0.01f * acc2;

        float part = h2 * s_w3[lane];
#pragma unroll
        for (int off = 16; off > 0; off >>= 1)
            part += __shfl_xor_sync(0xffffffffu, part, off);

        if (lane == 0) {
            float z = part + lb3[0];
            float sp = fmaxf(z, 0.0f) + log1pf(expf(-fabsf(z)));  // stable softplus
            g_conc[node] = sp;
            wsum += sp;                              // sp >= 0 => |sp| == sp
        }
    }

    if (lane == 0) s_blk[warp] = wsum;
    __syncthreads();
    if (tid == 0) {
        float s = 0.0f;
#pragma unroll
        for (int i = 0; i < 8; i++) s += s_blk[i];
        atomicAdd(&g_sum[0], s);
    }
}

// ------------------------- final: action + regularize ------------------------
__global__ void k_final(float* __restrict__ out, int n, int out_n) {
    int i = blockIdx.x * blockDim.x + threadIdx.x;
    float s = g_sum[0];
    if (i < n) out[i] = g_conc[i] / (s + 1e-20f);
    if (i == 0 && out_n > n) out[n] = s / (float)n;    // mean(|conc|)
}

// ------------------------- launch --------------------------------------------
extern "C" void kernel_launch(void* const* d_in, const int* in_sizes, int n_in,
                              void* d_out, int out_size) {
    const float* state = (const float*)d_in[0];
    const int*   ei    = (const int*)d_in[1];       // int32
    const float* W1 = (const float*)d_in[2];
    const float* b1 = (const float*)d_in[3];
    const float* W2 = (const float*)d_in[4];
    const float* b2 = (const float*)d_in[5];
    const float* W3 = (const float*)d_in[6];
    const float* b3 = (const float*)d_in[7];
    const float* lw1 = (const float*)d_in[8];
    const float* lb1 = (const float*)d_in[9];
    const float* lw2 = (const float*)d_in[10];
    const float* lb2 = (const float*)d_in[11];
    const float* lw3 = (const float*)d_in[12];
    const float* lb3 = (const float*)d_in[13];

    int n = in_sizes[0] / DD;        // 50000
    int E = in_sizes[1] / 2;         // 800000
    float* out = (float*)d_out;

    int nb_n = (n + 255) / 256;
    int nb_g = (n + 31) / 32;
    int nb_a = (n * 32 + 255) / 256;   // warp per node
    int nb_m = (n + 63) / 64;

    // CSR build: single resident-grid kernel (zero/count/scan/offset/place)
    k_csr<<<CSR_G, CSR_T>>>(ei, E, n);

    // layer 1
    k_gemm<<<nb_g, 256>>>(state, 0, W1, n);
    k_agg <<<nb_a, 256>>>(b1, 1, n);
    // layer 2
    k_gemm<<<nb_g, 256>>>(nullptr, 1, W2, n);
    k_agg <<<nb_a, 256>>>(b2, 2, n);
    // layer 3
    k_gemm<<<nb_g, 256>>>(nullptr, 2, W3, n);
    k_agg <<<nb_a, 256>>>(b3, 3, n);

    k_mlp  <<<nb_m, 256>>>(state, lw1, lb1, lw2, lb2, lw3, lb3, n);
    k_final<<<nb_n, 256>>>(out, n, out_size);
}

// round 12
// speedup vs baseline: 1.0499x; 1.0499x over previous
#include <cuda_runtime.h>
#include <cstdint>

#define NMAX 50000
#define EMAX 800000
#define DD 64
#define SCAN_B 1024
#define NBLK ((NMAX + SCAN_B - 1) / SCAN_B)   // 49

// ------------------------- scratch (__device__ globals; no allocs) ----------
__device__ int   g_cnt[NMAX];              // in-degree (without self-loop)
__device__ int   g_rs[NMAX];               // CSR row start (exclusive scan of cnt)
__device__ int   g_cur[NMAX];              // placement cursor
__device__ int   g_bsum[NBLK];             // scan block totals
__device__ __align__(16) float g_dinv[NMAX];
__device__ __align__(16) int2  g_edge[EMAX];   // CSR slot: {src, norm bits}
__device__ __align__(16) float g_h[NMAX * DD];
__device__ __align__(16) float g_out1[NMAX * DD];
__device__ __align__(16) float g_out2[NMAX * DD];
__device__ __align__(16) float g_out3[NMAX * DD];
__device__ float g_conc[NMAX];
__device__ float g_sum[1];

__device__ __forceinline__ int clampi(int v, int lo, int hi) {
    return v < lo ? lo : (v > hi ? hi : v);
}

// ------------------------- prep ---------------------------------------------
__global__ void k_zero(int n) {
    int i = blockIdx.x * blockDim.x + threadIdx.x;
    if (i < n) g_cnt[i] = 0;
    if (i == 0) g_sum[0] = 0.0f;
}

// edge_index is int32: layout [2, E] row-major
__global__ void k_count(const int* __restrict__ ei, int E, int n) {
    int e = blockIdx.x * blockDim.x + threadIdx.x;
    if (e >= E) return;
    int d = clampi(ei[E + e], 0, n - 1);
    atomicAdd(&g_cnt[d], 1);
}

// ---- scan phase 1: per-block exclusive scan + block totals (+ dinv fused) ---
__global__ void k_scan1(int n) {
    __shared__ int sh[SCAN_B];
    int t = threadIdx.x;
    int i = blockIdx.x * SCAN_B + t;
    int v = (i < n) ? g_cnt[i] : 0;
    if (i < n) g_dinv[i] = rsqrtf((float)v + 1.0f);   // fused degree norm
    sh[t] = v;
    __syncthreads();
    for (int off = 1; off < SCAN_B; off <<= 1) {
        int a = (t >= off) ? sh[t - off] : 0;
        __syncthreads();
        sh[t] += a;
        __syncthreads();
    }
    if (i < n) g_rs[i] = sh[t] - v;              // exclusive within block
    if (t == SCAN_B - 1) g_bsum[blockIdx.x] = sh[t];   // block total
}

// ---- scan phase 2: each block adds prefix over bsum[0..blockIdx.x) ----------
__global__ void k_scan3(int n, int nb) {
    __shared__ int sh64[64];
    __shared__ int s_off;
    int t = threadIdx.x;
    if (t < 64) {
        int v = (t < blockIdx.x && t < nb) ? g_bsum[t] : 0;
        sh64[t] = v;
    }
    __syncthreads();
    if (t < 32) {
        int v = sh64[t] + sh64[t + 32];
#pragma unroll
        for (int off = 16; off > 0; off >>= 1)
            v += __shfl_xor_sync(0xffffffffu, v, off);
        if (t == 0) s_off = v;
    }
    __syncthreads();
    int i = blockIdx.x * SCAN_B + t;
    if (i < n) {
        int v = g_rs[i] + s_off;
        g_rs[i] = v;
        g_cur[i] = v;
    }
}

// ---- CSR placement: packed {src, norm}: single 8B store per edge ------------
__global__ void k_place(const int* __restrict__ ei, int E, int n) {
    int e = blockIdx.x * blockDim.x + threadIdx.x;
    if (e >= E) return;
    int s = clampi(ei[e], 0, n - 1);
    int d = clampi(ei[E + e], 0, n - 1);
    int pos = atomicAdd(&g_cur[d], 1);
    float nrm = g_dinv[s] * g_dinv[d];
    g_edge[pos] = make_int2(s, __float_as_int(nrm));
}

// ------------------------- GEMM: g_h = x @ W ---------------------------------
// 256 threads, 64 rows/block; thread tile = 8 rows x 2 cols.
// Inner loop: 4 float2 W-LDS + 8 float4 x-LDS per 64 FFMA.
__global__ void k_gemm(const float* __restrict__ xext, int sel,
                       const float* __restrict__ W, int n) {
    __shared__ float Ws[DD * DD];      // 16 KB [k][c]
    __shared__ float xs[64 * DD];      // 16 KB [r][k]
    const float* x = (sel == 0) ? xext : (sel == 1 ? g_out1 : g_out2);

    int tid = threadIdx.x;
    {
        const float4* W4 = (const float4*)W;
        float4* Ws4 = (float4*)Ws;
#pragma unroll
        for (int i = 0; i < 4; i++) Ws4[tid + i * 256] = W4[tid + i * 256];
    }
    int row0 = blockIdx.x * 64;
    {
        if (row0 + 64 <= n) {
            const float4* x4 = (const float4*)(x + (size_t)row0 * DD);
            float4* xs4 = (float4*)xs;
#pragma unroll
            for (int i = 0; i < 4; i++) xs4[tid + i * 256] = x4[tid + i * 256];
        } else {
            int nrows = n - row0;
            for (int i = tid; i < nrows * DD; i += 256) xs[i] = x[(size_t)row0 * DD + i];
        }
    }
    __syncthreads();

    int c  = (tid & 31) * 2;           // col pair (adjacent)
    int r0 = (tid >> 5) * 8;           // 8-row group
    float acc0[8], acc1[8];
#pragma unroll
    for (int rr = 0; rr < 8; rr++) { acc0[rr] = 0.0f; acc1[rr] = 0.0f; }

#pragma unroll
    for (int kc = 0; kc < DD; kc += 4) {
        float2 w0 = *(const float2*)&Ws[(kc + 0) * DD + c];
        float2 w1 = *(const float2*)&Ws[(kc + 1) * DD + c];
        float2 w2 = *(const float2*)&Ws[(kc + 2) * DD + c];
        float2 w3 = *(const float2*)&Ws[(kc + 3) * DD + c];
#pragma unroll
        for (int rr = 0; rr < 8; rr++) {
            float4 xv = *(const float4*)&xs[(r0 + rr) * DD + kc];   // broadcast
            acc0[rr] += xv.x * w0.x + xv.y * w1.x + xv.z * w2.x + xv.w * w3.x;
            acc1[rr] += xv.x * w0.y + xv.y * w1.y + xv.z * w2.y + xv.w * w3.y;
        }
    }

#pragma unroll
    for (int rr = 0; rr < 8; rr++) {
        int r = row0 + r0 + rr;
        if (r < n)
            *(float2*)&g_h[(size_t)r * DD + c] = make_float2(acc0[rr], acc1[rr]);
    }
}

// ---- aggregate: out = relu( sum_in norm*h[src] + h[node]*dinv^2 + b ) -------
// warp per node; lane covers channels 2*lane, 2*lane+1 (float2);
// 4-edge pipelined loop, two accumulator pairs.
__global__ void k_agg(const float* __restrict__ b, int sel, int n) {
    int node = (int)((blockIdx.x * (unsigned)blockDim.x + threadIdx.x) >> 5);
    int lane = threadIdx.x & 31;
    if (node >= n) return;

    int ch = lane * 2;
    float di = g_dinv[node];
    float sl = di * di;
    float2 hv = *(const float2*)&g_h[node * DD + ch];
    float2 bb = *(const float2*)&b[ch];
    float a0 = hv.x * sl + bb.x;
    float a1 = hv.y * sl + bb.y;
    float c0 = 0.0f, c1 = 0.0f;

    int j   = g_rs[node];
    int end = j + g_cnt[node];

    if ((j & 1) && j < end) {
        int2 e0 = g_edge[j++];
        float n0 = __int_as_float(e0.y);
        float2 v0 = *(const float2*)&g_h[e0.x * DD + ch];
        a0 += n0 * v0.x;
        a1 += n0 * v0.y;
    }
    for (; j + 3 < end; j += 4) {
        int4 ea = *(const int4*)&g_edge[j];
        int4 eb = *(const int4*)&g_edge[j + 2];
        float n0 = __int_as_float(ea.y);
        float n1 = __int_as_float(ea.w);
        float n2 = __int_as_float(eb.y);
        float n3 = __int_as_float(eb.w);
        float2 v0 = *(const float2*)&g_h[ea.x * DD + ch];
        float2 v1 = *(const float2*)&g_h[ea.z * DD + ch];
        float2 v2 = *(const float2*)&g_h[eb.x * DD + ch];
        float2 v3 = *(const float2*)&g_h[eb.z * DD + ch];
        a0 += n0 * v0.x + n1 * v1.x;
        a1 += n0 * v0.y + n1 * v1.y;
        c0 += n2 * v2.x + n3 * v3.x;
        c1 += n2 * v2.y + n3 * v3.y;
    }
    if (j + 1 < end) {
        int4 ee = *(const int4*)&g_edge[j];
        float n0 = __int_as_float(ee.y);
        float n1 = __int_as_float(ee.w);
        float2 v0 = *(const float2*)&g_h[ee.x * DD + ch];
        float2 v1 = *(const float2*)&g_h[ee.z * DD + ch];
        a0 += n0 * v0.x + n1 * v1.x;
        a1 += n0 * v0.y + n1 * v1.y;
        j += 2;
    }
    if (j < end) {
        int2 e0 = g_edge[j];
        float n0 = __int_as_float(e0.y);
        float2 v0 = *(const float2*)&g_h[e0.x * DD + ch];
        a0 += n0 * v0.x;
        a1 += n0 * v0.y;
    }
    a0 += c0;
    a1 += c1;

    float* out = (sel == 1) ? g_out1 : (sel == 2 ? g_out2 : g_out3);
    *(float2*)&out[node * DD + ch] = make_float2(fmaxf(a0, 0.0f), fmaxf(a1, 0.0f));
}

// ------------------------- MLP head: GEMM-style layer1 -----------------------
// 256 threads = 8 warps; warp handles 8 nodes; lane = output column (32 outs).
__global__ void k_mlp(const float* __restrict__ state,
                      const float* __restrict__ lw1, const float* __restrict__ lb1,
                      const float* __restrict__ lw2, const float* __restrict__ lb2,
                      const float* __restrict__ lw3, const float* __restrict__ lb3,
                      int n) {
    __shared__ float s_w1[256 * 32];   // 32 KB  [k][o]
    __shared__ float s_w2[32 * 32];    // [i][o]
    __shared__ float s_w3[32];
    __shared__ float s_b1[32];
    __shared__ float s_b2[32];
    __shared__ float s_h1[64 * 32];    // 8 KB
    __shared__ float s_blk[8];

    int tid = threadIdx.x;
    {
        const float4* a = (const float4*)lw1;
        float4* d = (float4*)s_w1;
#pragma unroll
        for (int i = 0; i < 8; i++) d[tid + i * 256] = a[tid + i * 256];
    }
    for (int i = tid; i < 32 * 32; i += 256) s_w2[i] = lw2[i];
    if (tid < 32) { s_w3[tid] = lw3[tid]; s_b1[tid] = lb1[tid]; s_b2[tid] = lb2[tid]; }
    __syncthreads();

    int warp = tid >> 5, lane = tid & 31;
    int node0 = blockIdx.x * 64 + warp * 8;

    float acc[8];
#pragma unroll
    for (int rr = 0; rr < 8; rr++) acc[rr] = s_b1[lane];

    const float* segs[4] = {g_out1, g_out2, g_out3, state};
    bool full8 = (node0 + 8 <= n);

#pragma unroll
    for (int sg = 0; sg < 4; sg++) {
        const float* xp = segs[sg] + (size_t)node0 * DD;
#pragma unroll
        for (int kc = 0; kc < DD; kc += 4) {
            int k = sg * DD + kc;
            float w0 = s_w1[(k + 0) * 32 + lane];
            float w1 = s_w1[(k + 1) * 32 + lane];
            float w2 = s_w1[(k + 2) * 32 + lane];
            float w3 = s_w1[(k + 3) * 32 + lane];
            if (full8) {
#pragma unroll
                for (int rr = 0; rr < 8; rr++) {
                    float4 xv = *(const float4*)&xp[rr * DD + kc];  // warp-broadcast
                    acc[rr] += xv.x * w0 + xv.y * w1 + xv.z * w2 + xv.w * w3;
                }
            } else {
#pragma unroll
                for (int rr = 0; rr < 8; rr++) {
                    if (node0 + rr < n) {
                        float4 xv = *(const float4*)&xp[rr * DD + kc];
                        acc[rr] += xv.x * w0 + xv.y * w1 + xv.z * w2 + xv.w * w3;
                    }
                }
            }
        }
    }
#pragma unroll
    for (int rr = 0; rr < 8; rr++) {
        float v = acc[rr];
        s_h1[(warp * 8 + rr) * 32 + lane] = v > 0.0f ? v : 0.01f * v;
    }
    __syncwarp();

    float wsum = 0.0f;
#pragma unroll
    for (int rr = 0; rr < 8; rr++) {
        int node = node0 + rr;
        if (node >= n) break;
        const float* h1p = &s_h1[(warp * 8 + rr) * 32];
        float acc2 = s_b2[lane];
#pragma unroll
        for (int i = 0; i < 32; i++)
            acc2 += h1p[i] * s_w2[i * 32 + lane];    // h1p[i] LDS-broadcast
        float h2 = acc2 > 0.0f ? acc2 : 0.01f * acc2;

        float part = h2 * s_w3[lane];
#pragma unroll
        for (int off = 16; off > 0; off >>= 1)
            part += __shfl_xor_sync(0xffffffffu, part, off);

        if (lane == 0) {
            float z = part + lb3[0];
            float sp = fmaxf(z, 0.0f) + log1pf(expf(-fabsf(z)));  // stable softplus
            g_conc[node] = sp;
            wsum += sp;                              // sp >= 0 => |sp| == sp
        }
    }

    if (lane == 0) s_blk[warp] = wsum;
    __syncthreads();
    if (tid == 0) {
        float s = 0.0f;
#pragma unroll
        for (int i = 0; i < 8; i++) s += s_blk[i];
        atomicAdd(&g_sum[0], s);
    }
}

// ------------------------- final: action + regularize ------------------------
__global__ void k_final(float* __restrict__ out, int n, int out_n) {
    int i = blockIdx.x * blockDim.x + threadIdx.x;
    float s = g_sum[0];
    if (i < n) out[i] = g_conc[i] / (s + 1e-20f);
    if (i == 0 && out_n > n) out[n] = s / (float)n;    // mean(|conc|)
}

// ------------------------- launch --------------------------------------------
extern "C" void kernel_launch(void* const* d_in, const int* in_sizes, int n_in,
                              void* d_out, int out_size) {
    const float* state = (const float*)d_in[0];
    const int*   ei    = (const int*)d_in[1];       // int32
    const float* W1 = (const float*)d_in[2];
    const float* b1 = (const float*)d_in[3];
    const float* W2 = (const float*)d_in[4];
    const float* b2 = (const float*)d_in[5];
    const float* W3 = (const float*)d_in[6];
    const float* b3 = (const float*)d_in[7];
    const float* lw1 = (const float*)d_in[8];
    const float* lb1 = (const float*)d_in[9];
    const float* lw2 = (const float*)d_in[10];
    const float* lb2 = (const float*)d_in[11];
    const float* lw3 = (const float*)d_in[12];
    const float* lb3 = (const float*)d_in[13];

    int n = in_sizes[0] / DD;        // 50000
    int E = in_sizes[1] / 2;         // 800000
    float* out = (float*)d_out;

    int nb_n  = (n + 255) / 256;
    int nb_e  = (E + 255) / 256;
    int nb_sc = (n + SCAN_B - 1) / SCAN_B;
    int nb_g  = (n + 63) / 64;          // 64 rows per gemm block
    int nb_a  = (n * 32 + 255) / 256;   // warp per node
    int nb_m  = (n + 63) / 64;

    // CSR build (multi-kernel; R10 known-good)
    k_zero <<<nb_n, 256>>>(n);
    k_count<<<nb_e, 256>>>(ei, E, n);
    k_scan1<<<nb_sc, SCAN_B>>>(n);
    k_scan3<<<nb_sc, SCAN_B>>>(n, nb_sc);
    k_place<<<nb_e, 256>>>(ei, E, n);

    // layer 1
    k_gemm<<<nb_g, 256>>>(state, 0, W1, n);
    k_agg <<<nb_a, 256>>>(b1, 1, n);
    // layer 2
    k_gemm<<<nb_g, 256>>>(nullptr, 1, W2, n);
    k_agg <<<nb_a, 256>>>(b2, 2, n);
    // layer 3
    k_gemm<<<nb_g, 256>>>(nullptr, 2, W3, n);
    k_agg <<<nb_a, 256>>>(b3, 3, n);

    k_mlp  <<<nb_m, 256>>>(state, lw1, lb1, lw2, lb2, lw3, lb3, n);
    k_final<<<nb_n, 256>>>(out, n, out_size);
}

// round 14
// speedup vs baseline: 1.0965x; 1.0444x over previous
#include <cuda_runtime.h>
#include <cstdint>

#define NMAX 50000
#define EMAX 800000
#define DD 64
#define SCAN_B 1024
#define NBLK ((NMAX + SCAN_B - 1) / SCAN_B)   // 49

// ------------------------- scratch (__device__ globals; no allocs) ----------
__device__ int   g_cnt[NMAX];              // in-degree (without self-loop)
__device__ int   g_rs[NMAX];               // CSR row start (exclusive scan of cnt)
__device__ int   g_cur[NMAX];              // placement cursor
__device__ int   g_bsum[NBLK];             // scan block totals
__device__ __align__(16) float g_dinv[NMAX];
__device__ __align__(16) int2  g_edge[EMAX];   // CSR slot: {src, norm bits}
__device__ __align__(16) float g_h[NMAX * DD];
__device__ __align__(16) float g_out1[NMAX * DD];
__device__ __align__(16) float g_out2[NMAX * DD];
__device__ __align__(16) float g_out3[NMAX * DD];
__device__ float g_conc[NMAX];
__device__ float g_sum[1];

__device__ __forceinline__ int clampi(int v, int lo, int hi) {
    return v < lo ? lo : (v > hi ? hi : v);
}

// ------------------------- prep ---------------------------------------------
__global__ void k_zero(int n) {
    int i = blockIdx.x * blockDim.x + threadIdx.x;
    if (i < n) g_cnt[i] = 0;
    if (i == 0) g_sum[0] = 0.0f;
}

// edge_index is int32: layout [2, E] row-major
__global__ void k_count(const int* __restrict__ ei, int E, int n) {
    int e = blockIdx.x * blockDim.x + threadIdx.x;
    if (e >= E) return;
    int d = clampi(ei[E + e], 0, n - 1);
    atomicAdd(&g_cnt[d], 1);
}

// ---- scan phase 1: per-block exclusive scan + block totals (+ dinv fused) ---
__global__ void k_scan1(int n) {
    __shared__ int sh[SCAN_B];
    int t = threadIdx.x;
    int i = blockIdx.x * SCAN_B + t;
    int v = (i < n) ? g_cnt[i] : 0;
    if (i < n) g_dinv[i] = rsqrtf((float)v + 1.0f);   // fused degree norm
    sh[t] = v;
    __syncthreads();
    for (int off = 1; off < SCAN_B; off <<= 1) {
        int a = (t >= off) ? sh[t - off] : 0;
        __syncthreads();
        sh[t] += a;
        __syncthreads();
    }
    if (i < n) g_rs[i] = sh[t] - v;              // exclusive within block
    if (t == SCAN_B - 1) g_bsum[blockIdx.x] = sh[t];   // block total
}

// ---- scan phase 2: each block adds prefix over bsum[0..blockIdx.x) ----------
__global__ void k_scan3(int n, int nb) {
    __shared__ int sh64[64];
    __shared__ int s_off;
    int t = threadIdx.x;
    if (t < 64) {
        int v = (t < blockIdx.x && t < nb) ? g_bsum[t] : 0;
        sh64[t] = v;
    }
    __syncthreads();
    if (t < 32) {
        int v = sh64[t] + sh64[t + 32];
#pragma unroll
        for (int off = 16; off > 0; off >>= 1)
            v += __shfl_xor_sync(0xffffffffu, v, off);
        if (t == 0) s_off = v;
    }
    __syncthreads();
    int i = blockIdx.x * SCAN_B + t;
    if (i < n) {
        int v = g_rs[i] + s_off;
        g_rs[i] = v;
        g_cur[i] = v;
    }
}

// ---- CSR placement: packed {src, norm}: single 8B store per edge ------------
__global__ void k_place(const int* __restrict__ ei, int E, int n) {
    int e = blockIdx.x * blockDim.x + threadIdx.x;
    if (e >= E) return;
    int s = clampi(ei[e], 0, n - 1);
    int d = clampi(ei[E + e], 0, n - 1);
    int pos = atomicAdd(&g_cur[d], 1);
    float nrm = g_dinv[s] * g_dinv[d];
    g_edge[pos] = make_int2(s, __float_as_int(nrm));
}

// ------------------------- GEMM: g_h = x @ W ---------------------------------
// 256 threads, 128 rows/block; thread tile = 8 rows x 4 cols.
// Inner loop: 4 float4 W-LDS + 8 float4 x-LDS per 128 FFMA.
__global__ void k_gemm(const float* __restrict__ xext, int sel,
                       const float* __restrict__ W, int n) {
    __shared__ float Ws[DD * DD];       // 16 KB [k][c]
    __shared__ float xs[128 * DD];      // 32 KB [r][k]
    const float* x = (sel == 0) ? xext : (sel == 1 ? g_out1 : g_out2);

    int tid = threadIdx.x;
    {
        const float4* W4 = (const float4*)W;
        float4* Ws4 = (float4*)Ws;
#pragma unroll
        for (int i = 0; i < 4; i++) Ws4[tid + i * 256] = W4[tid + i * 256];
    }
    int row0 = blockIdx.x * 128;
    {
        if (row0 + 128 <= n) {
            const float4* x4 = (const float4*)(x + (size_t)row0 * DD);
            float4* xs4 = (float4*)xs;
#pragma unroll 8
            for (int i = 0; i < 8; i++) xs4[tid + i * 256] = x4[tid + i * 256];
        } else {
            int nrows = n - row0;
            for (int i = tid; i < nrows * DD; i += 256) xs[i] = x[(size_t)row0 * DD + i];
        }
    }
    __syncthreads();

    int c  = (tid & 15) * 4;            // 4 adjacent cols
    int r0 = (tid >> 4) * 8;            // 8-row group (16 groups -> 128 rows)
    float4 acc[8];
#pragma unroll
    for (int rr = 0; rr < 8; rr++) acc[rr] = make_float4(0.f, 0.f, 0.f, 0.f);

#pragma unroll
    for (int kc = 0; kc < DD; kc += 4) {
        float4 w0 = *(const float4*)&Ws[(kc + 0) * DD + c];
        float4 w1 = *(const float4*)&Ws[(kc + 1) * DD + c];
        float4 w2 = *(const float4*)&Ws[(kc + 2) * DD + c];
        float4 w3 = *(const float4*)&Ws[(kc + 3) * DD + c];
#pragma unroll
        for (int rr = 0; rr < 8; rr++) {
            float4 xv = *(const float4*)&xs[(r0 + rr) * DD + kc];   // broadcast
            acc[rr].x += xv.x * w0.x + xv.y * w1.x + xv.z * w2.x + xv.w * w3.x;
            acc[rr].y += xv.x * w0.y + xv.y * w1.y + xv.z * w2.y + xv.w * w3.y;
            acc[rr].z += xv.x * w0.z + xv.y * w1.z + xv.z * w2.z + xv.w * w3.z;
            acc[rr].w += xv.x * w0.w + xv.y * w1.w + xv.z * w2.w + xv.w * w3.w;
        }
    }

#pragma unroll
    for (int rr = 0; rr < 8; rr++) {
        int r = row0 + r0 + rr;
        if (r < n)
            *(float4*)&g_h[(size_t)r * DD + c] = acc[rr];
    }
}

// ---- aggregate: out = relu( sum_in norm*h[src] + h[node]*dinv^2 + b ) -------
// warp per node; lane covers channels 2*lane, 2*lane+1 (float2);
// 4-edge pipelined loop, two accumulator pairs.
__global__ void k_agg(const float* __restrict__ b, int sel, int n) {
    int node = (int)((blockIdx.x * (unsigned)blockDim.x + threadIdx.x) >> 5);
    int lane = threadIdx.x & 31;
    if (node >= n) return;

    int ch = lane * 2;
    float di = g_dinv[node];
    float sl = di * di;
    float2 hv = *(const float2*)&g_h[node * DD + ch];
    float2 bb = *(const float2*)&b[ch];
    float a0 = hv.x * sl + bb.x;
    float a1 = hv.y * sl + bb.y;
    float c0 = 0.0f, c1 = 0.0f;

    int j   = g_rs[node];
    int end = j + g_cnt[node];

    if ((j & 1) && j < end) {
        int2 e0 = g_edge[j++];
        float n0 = __int_as_float(e0.y);
        float2 v0 = *(const float2*)&g_h[e0.x * DD + ch];
        a0 += n0 * v0.x;
        a1 += n0 * v0.y;
    }
    for (; j + 3 < end; j += 4) {
        int4 ea = *(const int4*)&g_edge[j];
        int4 eb = *(const int4*)&g_edge[j + 2];
        float n0 = __int_as_float(ea.y);
        float n1 = __int_as_float(ea.w);
        float n2 = __int_as_float(eb.y);
        float n3 = __int_as_float(eb.w);
        float2 v0 = *(const float2*)&g_h[ea.x * DD + ch];
        float2 v1 = *(const float2*)&g_h[ea.z * DD + ch];
        float2 v2 = *(const float2*)&g_h[eb.x * DD + ch];
        float2 v3 = *(const float2*)&g_h[eb.z * DD + ch];
        a0 += n0 * v0.x + n1 * v1.x;
        a1 += n0 * v0.y + n1 * v1.y;
        c0 += n2 * v2.x + n3 * v3.x;
        c1 += n2 * v2.y + n3 * v3.y;
    }
    if (j + 1 < end) {
        int4 ee = *(const int4*)&g_edge[j];
        float n0 = __int_as_float(ee.y);
        float n1 = __int_as_float(ee.w);
        float2 v0 = *(const float2*)&g_h[ee.x * DD + ch];
        float2 v1 = *(const float2*)&g_h[ee.z * DD + ch];
        a0 += n0 * v0.x + n1 * v1.x;
        a1 += n0 * v0.y + n1 * v1.y;
        j += 2;
    }
    if (j < end) {
        int2 e0 = g_edge[j];
        float n0 = __int_as_float(e0.y);
        float2 v0 = *(const float2*)&g_h[e0.x * DD + ch];
        a0 += n0 * v0.x;
        a1 += n0 * v0.y;
    }
    a0 += c0;
    a1 += c1;

    float* out = (sel == 1) ? g_out1 : (sel == 2 ? g_out2 : g_out3);
    *(float2*)&out[node * DD + ch] = make_float2(fmaxf(a0, 0.0f), fmaxf(a1, 0.0f));
}

// ------------------------- MLP head: GEMM-style layer1 -----------------------
// 256 threads = 8 warps; warp handles 8 nodes; lane = output column (32 outs).
__global__ void k_mlp(const float* __restrict__ state,
                      const float* __restrict__ lw1, const float* __restrict__ lb1,
                      const float* __restrict__ lw2, const float* __restrict__ lb2,
                      const float* __restrict__ lw3, const float* __restrict__ lb3,
                      int n) {
    __shared__ float s_w1[256 * 32];   // 32 KB  [k][o]
    __shared__ float s_w2[32 * 32];    // [i][o]
    __shared__ float s_w3[32];
    __shared__ float s_b1[32];
    __shared__ float s_b2[32];
    __shared__ float s_h1[64 * 32];    // 8 KB
    __shared__ float s_blk[8];

    int tid = threadIdx.x;
    {
        const float4* a = (const float4*)lw1;
        float4* d = (float4*)s_w1;
#pragma unroll
        for (int i = 0; i < 8; i++) d[tid + i * 256] = a[tid + i * 256];
    }
    for (int i = tid; i < 32 * 32; i += 256) s_w2[i] = lw2[i];
    if (tid < 32) { s_w3[tid] = lw3[tid]; s_b1[tid] = lb1[tid]; s_b2[tid] = lb2[tid]; }
    __syncthreads();

    int warp = tid >> 5, lane = tid & 31;
    int node0 = blockIdx.x * 64 + warp * 8;

    float acc[8];
#pragma unroll
    for (int rr = 0; rr < 8; rr++) acc[rr] = s_b1[lane];

    const float* segs[4] = {g_out1, g_out2, g_out3, state};
    bool full8 = (node0 + 8 <= n);

#pragma unroll
    for (int sg = 0; sg < 4; sg++) {
        const float* xp = segs[sg] + (size_t)node0 * DD;
#pragma unroll
        for (int kc = 0; kc < DD; kc += 4) {
            int k = sg * DD + kc;
            float w0 = s_w1[(k + 0) * 32 + lane];
            float w1 = s_w1[(k + 1) * 32 + lane];
            float w2 = s_w1[(k + 2) * 32 + lane];
            float w3 = s_w1[(k + 3) * 32 + lane];
            if (full8) {
#pragma unroll
                for (int rr = 0; rr < 8; rr++) {
                    float4 xv = *(const float4*)&xp[rr * DD + kc];  // warp-broadcast
                    acc[rr] += xv.x * w0 + xv.y * w1 + xv.z * w2 + xv.w * w3;
                }
            } else {
#pragma unroll
                for (int rr = 0; rr < 8; rr++) {
                    if (node0 + rr < n) {
                        float4 xv = *(const float4*)&xp[rr * DD + kc];
                        acc[rr] += xv.x * w0 + xv.y * w1 + xv.z * w2 + xv.w * w3;
                    }
                }
            }
        }
    }
#pragma unroll
    for (int rr = 0; rr < 8; rr++) {
        float v = acc[rr];
        s_h1[(warp * 8 + rr) * 32 + lane] = v > 0.0f ? v : 0.01f * v;
    }
    __syncwarp();

    float wsum = 0.0f;
#pragma unroll
    for (int rr = 0; rr < 8; rr++) {
        int node = node0 + rr;
        if (node >= n) break;
        const float* h1p = &s_h1[(warp * 8 + rr) * 32];
        float acc2 = s_b2[lane];
#pragma unroll
        for (int i = 0; i < 32; i++)
            acc2 += h1p[i] * s_w2[i * 32 + lane];    // h1p[i] LDS-broadcast
        float h2 = acc2 > 0.0f ? acc2 : 0.01f * acc2;

        float part = h2 * s_w3[lane];
#pragma unroll
        for (int off = 16; off > 0; off >>= 1)
            part += __shfl_xor_sync(0xffffffffu, part, off);

        if (lane == 0) {
            float z = part + lb3[0];
            float sp = fmaxf(z, 0.0f) + log1pf(expf(-fabsf(z)));  // stable softplus
            g_conc[node] = sp;
            wsum += sp;                              // sp >= 0 => |sp| == sp
        }
    }

    if (lane == 0) s_blk[warp] = wsum;
    __syncthreads();
    if (tid == 0) {
        float s = 0.0f;
#pragma unroll
        for (int i = 0; i < 8; i++) s += s_blk[i];
        atomicAdd(&g_sum[0], s);
    }
}

// ------------------------- final: action + regularize ------------------------
__global__ void k_final(float* __restrict__ out, int n, int out_n) {
    int i = blockIdx.x * blockDim.x + threadIdx.x;
    float s = g_sum[0];
    if (i < n) out[i] = g_conc[i] / (s + 1e-20f);
    if (i == 0 && out_n > n) out[n] = s / (float)n;    // mean(|conc|)
}

// ------------------------- launch --------------------------------------------
extern "C" void kernel_launch(void* const* d_in, const int* in_sizes, int n_in,
                              void* d_out, int out_size) {
    const float* state = (const float*)d_in[0];
    const int*   ei    = (const int*)d_in[1];       // int32
    const float* W1 = (const float*)d_in[2];
    const float* b1 = (const float*)d_in[3];
    const float* W2 = (const float*)d_in[4];
    const float* b2 = (const float*)d_in[5];
    const float* W3 = (const float*)d_in[6];
    const float* b3 = (const float*)d_in[7];
    const float* lw1 = (const float*)d_in[8];
    const float* lb1 = (const float*)d_in[9];
    const float* lw2 = (const float*)d_in[10];
    const float* lb2 = (const float*)d_in[11];
    const float* lw3 = (const float*)d_in[12];
    const float* lb3 = (const float*)d_in[13];

    int n = in_sizes[0] / DD;        // 50000
    int E = in_sizes[1] / 2;         // 800000
    float* out = (float*)d_out;

    int nb_n  = (n + 255) / 256;
    int nb_e  = (E + 255) / 256;
    int nb_sc = (n + SCAN_B - 1) / SCAN_B;
    int nb_g  = (n + 127) / 128;        // 128 rows per gemm block
    int nb_a  = (n * 32 + 255) / 256;   // warp per node
    int nb_m  = (n + 63) / 64;

    // CSR build (multi-kernel; known-good)
    k_zero <<<nb_n, 256>>>(n);
    k_count<<<nb_e, 256>>>(ei, E, n);
    k_scan1<<<nb_sc, SCAN_B>>>(n);
    k_scan3<<<nb_sc, SCAN_B>>>(n, nb_sc);
    k_place<<<nb_e, 256>>>(ei, E, n);

    // layer 1
    k_gemm<<<nb_g, 256>>>(state, 0, W1, n);
    k_agg <<<nb_a, 256>>>(b1, 1, n);
    // layer 2
    k_gemm<<<nb_g, 256>>>(nullptr, 1, W2, n);
    k_agg <<<nb_a, 256>>>(b2, 2, n);
    // layer 3
    k_gemm<<<nb_g, 256>>>(nullptr, 2, W3, n);
    k_agg <<<nb_a, 256>>>(b3, 3, n);

    k_mlp  <<<nb_m, 256>>>(state, lw1, lb1, lw2, lb2, lw3, lb3, n);
    k_final<<<nb_n, 256>>>(out, n, out_size);
}